// round 9
// baseline (speedup 1.0000x reference)
#include <cuda_runtime.h>

#define H_ 256
#define W_ 256
#define PIX (H_ * W_)
#define MAXB 8
#define TPB 512
#define OCC 3
#define NBLOCKS (OCC * 148)   // 444: proven co-resident via __launch_bounds__(512,3)

__device__ float g_proj[MAXB * PIX];   // zero at load; re-zeroed by each launch
__device__ float g_sum;
__device__ unsigned int g_count;
__device__ unsigned int g_bar1;
__device__ unsigned int g_bar2;

// process one point; corner hits -> register accumulators c00..c11,
// edge hits -> smem border bins, interior -> global atomics
#define PROC(xx, yy, zz, dd) do {                                         \
    if ((dd) > 0.5f) {                                                    \
        float r256 = 256.0f / (zz);                                       \
        float fu = fmaf((xx), r256, 128.0f);                              \
        float fv = fmaf((yy), r256, 128.0f);                              \
        int u = min(max((int)fu, 0), W_ - 1);                             \
        int v = min(max((int)fv, 0), H_ - 1);                             \
        float val = (zz) * (dd);                                          \
        bool uc = (u == 0) | (u == W_ - 1);                               \
        bool vc = (v == 0) | (v == H_ - 1);                               \
        if (uc & vc) {                                                    \
            if (v == 0) { if (u == 0) c00 += val; else c01 += val; }      \
            else        { if (u == 0) c10 += val; else c11 += val; }      \
        } else if (vc) {                                                  \
            atomicAdd(&sb[(v == 0 ? 0 : 256) + u], val);                  \
        } else if (uc) {                                                  \
            atomicAdd(&sb[(u == 0 ? 512 : 768) + v], val);                \
        } else {                                                          \
            atomicAdd(&g_proj[bpix + v * W_ + u], val);                   \
        }                                                                 \
    }                                                                     \
} while (0)

__global__ void __launch_bounds__(TPB, OCC)
fused_kernel(const float* __restrict__ pts,
             const float* __restrict__ dens,
             const float* __restrict__ depth,
             float* __restrict__ out,
             int N, int B, int blocksPerBatch, int nblocks) {
    __shared__ float sb[1024];
    for (int k = threadIdx.x; k < 1024; k += TPB) sb[k] = 0.0f;
    __syncthreads();

    // ---------------- Phase A: scatter ----------------
    const int b   = blockIdx.x / blocksPerBatch;
    const int blk = blockIdx.x % blocksPerBatch;
    const int bpix = b * PIX;
    const float4* __restrict__ pts4  = (const float4*)(pts  + (long)b * N * 3);
    const float4* __restrict__ dens4 = (const float4*)(dens + (long)b * N);

    float c00 = 0.0f, c01 = 0.0f, c10 = 0.0f, c11 = 0.0f;

    const int NQ = N >> 2;                 // quads (N divisible by 4)
    const int stride = blocksPerBatch * TPB;
    for (int q = blk * TPB + threadIdx.x; q < NQ; q += stride) {
        float4 dv = dens4[q];
        if (dv.x <= 0.5f && dv.y <= 0.5f && dv.z <= 0.5f && dv.w <= 0.5f)
            continue;
        float4 p0 = pts4[3 * q + 0];
        float4 p1 = pts4[3 * q + 1];
        float4 p2 = pts4[3 * q + 2];
        PROC(p0.x, p0.y, p0.z, dv.x);
        PROC(p0.w, p1.x, p1.y, dv.y);
        PROC(p1.z, p1.w, p2.x, dv.z);
        PROC(p2.y, p2.z, p2.w, dv.w);
    }
    // scalar tail (empty for N=500000; kept for safety)
    for (int p = 4 * NQ + blk * TPB + threadIdx.x; p < N; p += stride) {
        long i = (long)b * N + p;
        float dd = dens[i];
        if (dd > 0.5f) {
            float xx = pts[3 * i + 0], yy = pts[3 * i + 1], zz = pts[3 * i + 2];
            PROC(xx, yy, zz, dd);
        }
    }

    // fold corner registers into smem border bins
    #pragma unroll
    for (int o = 16; o > 0; o >>= 1) {
        c00 += __shfl_down_sync(0xffffffffu, c00, o);
        c01 += __shfl_down_sync(0xffffffffu, c01, o);
        c10 += __shfl_down_sync(0xffffffffu, c10, o);
        c11 += __shfl_down_sync(0xffffffffu, c11, o);
    }
    if ((threadIdx.x & 31) == 0) {
        if (c00 != 0.0f) atomicAdd(&sb[0],   c00);
        if (c01 != 0.0f) atomicAdd(&sb[255], c01);
        if (c10 != 0.0f) atomicAdd(&sb[256], c10);
        if (c11 != 0.0f) atomicAdd(&sb[511], c11);
    }
    __syncthreads();

    // flush border bins to global
    for (int k = threadIdx.x; k < 1024; k += TPB) {
        float s = sb[k];
        if (s != 0.0f) {
            int u, v;
            if (k < 256)      { v = 0;       u = k; }
            else if (k < 512) { v = H_ - 1;  u = k - 256; }
            else if (k < 768) { u = 0;       v = k - 512; }
            else              { u = W_ - 1;  v = k - 768; }
            atomicAdd(&g_proj[bpix + v * W_ + u], s);
        }
    }

    // ---------------- grid barrier ----------------
    __threadfence();
    __syncthreads();
    if (threadIdx.x == 0) {
        atomicAdd(&g_bar1, 1u);
        while (*(volatile unsigned int*)&g_bar1 < (unsigned int)nblocks) { }
    }
    __syncthreads();
    __threadfence();

    // ---------------- Phase B: reduce + re-zero ----------------
    const int total = B * PIX;
    float s = 0.0f;
    unsigned int c = 0u;
    for (int i = blockIdx.x * TPB + threadIdx.x; i < total; i += nblocks * TPB) {
        float p = g_proj[i];
        g_proj[i] = 0.0f;                 // leave scratch clean for next replay
        if (p > 0.0f) {
            float diff = p - depth[i];
            s += diff * diff;
            c += 1u;
        }
    }
    #pragma unroll
    for (int o = 16; o > 0; o >>= 1) {
        s += __shfl_down_sync(0xffffffffu, s, o);
        c += __shfl_down_sync(0xffffffffu, c, o);
    }
    __shared__ float ss[16];
    __shared__ unsigned int scnt[16];
    int lane = threadIdx.x & 31;
    int wid = threadIdx.x >> 5;
    if (lane == 0) { ss[wid] = s; scnt[wid] = c; }
    __syncthreads();
    if (wid == 0) {
        s = (lane < (TPB >> 5)) ? ss[lane] : 0.0f;
        c = (lane < (TPB >> 5)) ? scnt[lane] : 0u;
        #pragma unroll
        for (int o = 8; o > 0; o >>= 1) {
            s += __shfl_down_sync(0xffffffffu, s, o);
            c += __shfl_down_sync(0xffffffffu, c, o);
        }
        if (lane == 0) {
            atomicAdd(&g_sum, s);
            atomicAdd(&g_count, c);
        }
    }

    // ---------------- finalize (last block) ----------------
    __threadfence();
    if (threadIdx.x == 0) {
        unsigned int prev = atomicAdd(&g_bar2, 1u);
        if (prev == (unsigned int)nblocks - 1u) {
            float fs = *(volatile float*)&g_sum;
            unsigned int fc = *(volatile unsigned int*)&g_count;
            if (fc < 1u) fc = 1u;
            out[0] = fs / (float)fc;
            // reset state for next replay (all bar1 spinners have exited:
            // every block incremented bar2 only after passing bar1)
            g_sum = 0.0f;
            g_count = 0u;
            g_bar1 = 0u;
            g_bar2 = 0u;
        }
    }
}

extern "C" void kernel_launch(void* const* d_in, const int* in_sizes, int n_in,
                              void* d_out, int out_size) {
    const float* points = (const float*)d_in[0];   // (B, N, 3)
    const float* dens   = (const float*)d_in[1];   // (B, N, 1)
    const float* depth  = (const float*)d_in[2];   // (B, 1, H, W)
    float* out = (float*)d_out;

    int B = in_sizes[2] / PIX;                     // 8
    int N = in_sizes[0] / (3 * B);                 // 500000

    int blocksPerBatch = NBLOCKS / B;              // 55
    if (blocksPerBatch < 1) blocksPerBatch = 1;
    int nblocks = blocksPerBatch * B;              // 440 for B=8

    fused_kernel<<<nblocks, TPB>>>(points, dens, depth, out,
                                   N, B, blocksPerBatch, nblocks);
}

// round 12
// speedup vs baseline: 1.4146x; 1.4146x over previous
#include <cuda_runtime.h>

#define H_ 256
#define W_ 256
#define PIX (H_ * W_)
#define MAXB 8
#define TPB 512
#define OCC 3
#define NBLOCKS (OCC * 148)   // 444: proven co-resident via __launch_bounds__(512,3)

__device__ float g_proj[MAXB * PIX];   // zero at load; re-zeroed by each launch
__device__ float g_sum;
__device__ unsigned int g_count;
__device__ unsigned int g_bar1;
__device__ unsigned int g_bar2;

// process one point; corner hits -> register accumulators c00..c11,
// edge hits -> smem border bins, interior -> global atomics
// fast divide: RCP+MUL instead of full-precision Newton chain
#define PROC(xx, yy, zz, dd) do {                                         \
    if ((dd) > 0.5f) {                                                    \
        float r256 = __fdividef(256.0f, (zz));                            \
        float fu = fmaf((xx), r256, 128.0f);                              \
        float fv = fmaf((yy), r256, 128.0f);                              \
        int u = min(max((int)fu, 0), W_ - 1);                             \
        int v = min(max((int)fv, 0), H_ - 1);                             \
        float val = (zz) * (dd);                                          \
        bool uc = (u == 0) | (u == W_ - 1);                               \
        bool vc = (v == 0) | (v == H_ - 1);                               \
        if (uc & vc) {                                                    \
            if (v == 0) { if (u == 0) c00 += val; else c01 += val; }      \
            else        { if (u == 0) c10 += val; else c11 += val; }      \
        } else if (vc) {                                                  \
            atomicAdd(&sb[(v == 0 ? 0 : 256) + u], val);                  \
        } else if (uc) {                                                  \
            atomicAdd(&sb[(u == 0 ? 512 : 768) + v], val);                \
        } else {                                                          \
            atomicAdd(&g_proj[bpix + v * W_ + u], val);                   \
        }                                                                 \
    }                                                                     \
} while (0)

__global__ void __launch_bounds__(TPB, OCC)
fused_kernel(const float* __restrict__ pts,
             const float* __restrict__ dens,
             const float* __restrict__ depth,
             float* __restrict__ out,
             int N, int B, int blocksPerBatch, int nblocks) {
    __shared__ float sb[1024];
    for (int k = threadIdx.x; k < 1024; k += TPB) sb[k] = 0.0f;
    __syncthreads();

    // ---------------- Phase A: scatter ----------------
    const int b   = blockIdx.x / blocksPerBatch;
    const int blk = blockIdx.x % blocksPerBatch;
    const int bpix = b * PIX;
    const float4* __restrict__ pts4  = (const float4*)(pts  + (long)b * N * 3);
    const float4* __restrict__ dens4 = (const float4*)(dens + (long)b * N);

    float c00 = 0.0f, c01 = 0.0f, c10 = 0.0f, c11 = 0.0f;

    const int NQ = N >> 2;                 // quads (N divisible by 4)
    const int stride = blocksPerBatch * TPB;
    for (int q = blk * TPB + threadIdx.x; q < NQ; q += stride) {
        float4 dv = dens4[q];
        if (dv.x <= 0.5f && dv.y <= 0.5f && dv.z <= 0.5f && dv.w <= 0.5f)
            continue;
        float4 p0 = pts4[3 * q + 0];
        float4 p1 = pts4[3 * q + 1];
        float4 p2 = pts4[3 * q + 2];
        PROC(p0.x, p0.y, p0.z, dv.x);
        PROC(p0.w, p1.x, p1.y, dv.y);
        PROC(p1.z, p1.w, p2.x, dv.z);
        PROC(p2.y, p2.z, p2.w, dv.w);
    }
    // scalar tail (empty for N=500000; kept for safety)
    for (int p = 4 * NQ + blk * TPB + threadIdx.x; p < N; p += stride) {
        long i = (long)b * N + p;
        float dd = dens[i];
        if (dd > 0.5f) {
            float xx = pts[3 * i + 0], yy = pts[3 * i + 1], zz = pts[3 * i + 2];
            PROC(xx, yy, zz, dd);
        }
    }

    // fold corner registers into smem border bins
    #pragma unroll
    for (int o = 16; o > 0; o >>= 1) {
        c00 += __shfl_down_sync(0xffffffffu, c00, o);
        c01 += __shfl_down_sync(0xffffffffu, c01, o);
        c10 += __shfl_down_sync(0xffffffffu, c10, o);
        c11 += __shfl_down_sync(0xffffffffu, c11, o);
    }
    if ((threadIdx.x & 31) == 0) {
        if (c00 != 0.0f) atomicAdd(&sb[0],   c00);
        if (c01 != 0.0f) atomicAdd(&sb[255], c01);
        if (c10 != 0.0f) atomicAdd(&sb[256], c10);
        if (c11 != 0.0f) atomicAdd(&sb[511], c11);
    }
    __syncthreads();

    // flush border bins to global
    for (int k = threadIdx.x; k < 1024; k += TPB) {
        float s = sb[k];
        if (s != 0.0f) {
            int u, v;
            if (k < 256)      { v = 0;       u = k; }
            else if (k < 512) { v = H_ - 1;  u = k - 256; }
            else if (k < 768) { u = 0;       v = k - 512; }
            else              { u = W_ - 1;  v = k - 768; }
            atomicAdd(&g_proj[bpix + v * W_ + u], s);
        }
    }

    // ---------------- grid barrier ----------------
    __threadfence();
    __syncthreads();
    if (threadIdx.x == 0) {
        atomicAdd(&g_bar1, 1u);
        while (*(volatile unsigned int*)&g_bar1 < (unsigned int)nblocks) { }
    }
    __syncthreads();
    __threadfence();

    // ---------------- Phase B: reduce + re-zero ----------------
    const int total = B * PIX;
    float s = 0.0f;
    unsigned int c = 0u;
    for (int i = blockIdx.x * TPB + threadIdx.x; i < total; i += nblocks * TPB) {
        float p = g_proj[i];
        g_proj[i] = 0.0f;                 // leave scratch clean for next replay
        if (p > 0.0f) {
            float diff = p - depth[i];
            s += diff * diff;
            c += 1u;
        }
    }
    #pragma unroll
    for (int o = 16; o > 0; o >>= 1) {
        s += __shfl_down_sync(0xffffffffu, s, o);
        c += __shfl_down_sync(0xffffffffu, c, o);
    }
    __shared__ float ss[16];
    __shared__ unsigned int scnt[16];
    int lane = threadIdx.x & 31;
    int wid = threadIdx.x >> 5;
    if (lane == 0) { ss[wid] = s; scnt[wid] = c; }
    __syncthreads();
    if (wid == 0) {
        s = (lane < (TPB >> 5)) ? ss[lane] : 0.0f;
        c = (lane < (TPB >> 5)) ? scnt[lane] : 0u;
        #pragma unroll
        for (int o = 8; o > 0; o >>= 1) {
            s += __shfl_down_sync(0xffffffffu, s, o);
            c += __shfl_down_sync(0xffffffffu, c, o);
        }
        if (lane == 0) {
            atomicAdd(&g_sum, s);
            atomicAdd(&g_count, c);
        }
    }

    // ---------------- finalize (last block) ----------------
    __threadfence();
    if (threadIdx.x == 0) {
        unsigned int prev = atomicAdd(&g_bar2, 1u);
        if (prev == (unsigned int)nblocks - 1u) {
            float fs = *(volatile float*)&g_sum;
            unsigned int fc = *(volatile unsigned int*)&g_count;
            if (fc < 1u) fc = 1u;
            out[0] = fs / (float)fc;
            // reset state for next replay (all bar1 spinners have exited:
            // every block incremented bar2 only after passing bar1)
            g_sum = 0.0f;
            g_count = 0u;
            g_bar1 = 0u;
            g_bar2 = 0u;
        }
    }
}

extern "C" void kernel_launch(void* const* d_in, const int* in_sizes, int n_in,
                              void* d_out, int out_size) {
    const float* points = (const float*)d_in[0];   // (B, N, 3)
    const float* dens   = (const float*)d_in[1];   // (B, N, 1)
    const float* depth  = (const float*)d_in[2];   // (B, 1, H, W)
    float* out = (float*)d_out;

    int B = in_sizes[2] / PIX;                     // 8
    int N = in_sizes[0] / (3 * B);                 // 500000

    int blocksPerBatch = NBLOCKS / B;              // 55
    if (blocksPerBatch < 1) blocksPerBatch = 1;
    int nblocks = blocksPerBatch * B;              // 440 for B=8

    fused_kernel<<<nblocks, TPB>>>(points, dens, depth, out,
                                   N, B, blocksPerBatch, nblocks);
}

// round 14
// speedup vs baseline: 1.4477x; 1.0234x over previous
#include <cuda_runtime.h>

#define H_ 256
#define W_ 256
#define PIX (H_ * W_)
#define MAXB 8
#define TPB 512
#define OCC 3
#define NBLOCKS (OCC * 148)   // 444: proven co-resident via __launch_bounds__(512,3)

__device__ float g_proj[MAXB * PIX];   // zero at load; re-zeroed by each launch
__device__ float g_sum;
__device__ unsigned int g_count;
__device__ unsigned int g_bar1;
__device__ unsigned int g_bar2;

// process one point; corner hits -> register accumulators c00..c11,
// edge hits -> smem border bins, interior -> global atomics
#define PROC(xx, yy, zz, dd) do {                                         \
    if ((dd) > 0.5f) {                                                    \
        float r256 = __fdividef(256.0f, (zz));                            \
        float fu = fmaf((xx), r256, 128.0f);                              \
        float fv = fmaf((yy), r256, 128.0f);                              \
        int u = min(max((int)fu, 0), W_ - 1);                             \
        int v = min(max((int)fv, 0), H_ - 1);                             \
        float val = (zz) * (dd);                                          \
        bool uc = (u == 0) | (u == W_ - 1);                               \
        bool vc = (v == 0) | (v == H_ - 1);                               \
        if (uc & vc) {                                                    \
            if (v == 0) { if (u == 0) c00 += val; else c01 += val; }      \
            else        { if (u == 0) c10 += val; else c11 += val; }      \
        } else if (vc) {                                                  \
            atomicAdd(&sb[(v == 0 ? 0 : 256) + u], val);                  \
        } else if (uc) {                                                  \
            atomicAdd(&sb[(u == 0 ? 512 : 768) + v], val);                \
        } else {                                                          \
            atomicAdd(&g_proj[bpix + v * W_ + u], val);                   \
        }                                                                 \
    }                                                                     \
} while (0)

__global__ void __launch_bounds__(TPB, OCC)
fused_kernel(const float* __restrict__ pts,
             const float* __restrict__ dens,
             const float* __restrict__ depth,
             float* __restrict__ out,
             int N, int B, int blocksPerBatch, int nblocks) {
    __shared__ float sb[1024];
    for (int k = threadIdx.x; k < 1024; k += TPB) sb[k] = 0.0f;
    __syncthreads();

    // ---------------- Phase A: scatter ----------------
    const int b   = blockIdx.x / blocksPerBatch;
    const int blk = blockIdx.x % blocksPerBatch;
    const int bpix = b * PIX;
    const float4* __restrict__ pts4  = (const float4*)(pts  + (long)b * N * 3);
    const float4* __restrict__ dens4 = (const float4*)(dens + (long)b * N);

    float c00 = 0.0f, c01 = 0.0f, c10 = 0.0f, c11 = 0.0f;

    const int NQ = N >> 2;                 // quads (N divisible by 4)
    const int stride = blocksPerBatch * TPB;
    for (int q = blk * TPB + threadIdx.x; q < NQ; q += stride) {
        // All four 16B loads issued back-to-back, no intervening branch:
        // MLP_p1 = 4 (was 1 with the early-skip on density).
        float4 dv = dens4[q];
        float4 p0 = pts4[3 * q + 0];
        float4 p1 = pts4[3 * q + 1];
        float4 p2 = pts4[3 * q + 2];
        PROC(p0.x, p0.y, p0.z, dv.x);
        PROC(p0.w, p1.x, p1.y, dv.y);
        PROC(p1.z, p1.w, p2.x, dv.z);
        PROC(p2.y, p2.z, p2.w, dv.w);
    }
    // scalar tail (empty for N=500000; kept for safety)
    for (int p = 4 * NQ + blk * TPB + threadIdx.x; p < N; p += stride) {
        long i = (long)b * N + p;
        float dd = dens[i];
        if (dd > 0.5f) {
            float xx = pts[3 * i + 0], yy = pts[3 * i + 1], zz = pts[3 * i + 2];
            PROC(xx, yy, zz, dd);
        }
    }

    // fold corner registers into smem border bins
    #pragma unroll
    for (int o = 16; o > 0; o >>= 1) {
        c00 += __shfl_down_sync(0xffffffffu, c00, o);
        c01 += __shfl_down_sync(0xffffffffu, c01, o);
        c10 += __shfl_down_sync(0xffffffffu, c10, o);
        c11 += __shfl_down_sync(0xffffffffu, c11, o);
    }
    if ((threadIdx.x & 31) == 0) {
        if (c00 != 0.0f) atomicAdd(&sb[0],   c00);
        if (c01 != 0.0f) atomicAdd(&sb[255], c01);
        if (c10 != 0.0f) atomicAdd(&sb[256], c10);
        if (c11 != 0.0f) atomicAdd(&sb[511], c11);
    }
    __syncthreads();

    // flush border bins to global
    for (int k = threadIdx.x; k < 1024; k += TPB) {
        float s = sb[k];
        if (s != 0.0f) {
            int u, v;
            if (k < 256)      { v = 0;       u = k; }
            else if (k < 512) { v = H_ - 1;  u = k - 256; }
            else if (k < 768) { u = 0;       v = k - 512; }
            else              { u = W_ - 1;  v = k - 768; }
            atomicAdd(&g_proj[bpix + v * W_ + u], s);
        }
    }

    // ---------------- grid barrier ----------------
    __threadfence();
    __syncthreads();
    if (threadIdx.x == 0) {
        atomicAdd(&g_bar1, 1u);
        while (*(volatile unsigned int*)&g_bar1 < (unsigned int)nblocks) { }
    }
    __syncthreads();
    __threadfence();

    // ---------------- Phase B: reduce + re-zero ----------------
    const int total = B * PIX;
    float s = 0.0f;
    unsigned int c = 0u;
    for (int i = blockIdx.x * TPB + threadIdx.x; i < total; i += nblocks * TPB) {
        float p = g_proj[i];
        g_proj[i] = 0.0f;                 // leave scratch clean for next replay
        if (p > 0.0f) {
            float diff = p - depth[i];
            s += diff * diff;
            c += 1u;
        }
    }
    #pragma unroll
    for (int o = 16; o > 0; o >>= 1) {
        s += __shfl_down_sync(0xffffffffu, s, o);
        c += __shfl_down_sync(0xffffffffu, c, o);
    }
    __shared__ float ss[16];
    __shared__ unsigned int scnt[16];
    int lane = threadIdx.x & 31;
    int wid = threadIdx.x >> 5;
    if (lane == 0) { ss[wid] = s; scnt[wid] = c; }
    __syncthreads();
    if (wid == 0) {
        s = (lane < (TPB >> 5)) ? ss[lane] : 0.0f;
        c = (lane < (TPB >> 5)) ? scnt[lane] : 0u;
        #pragma unroll
        for (int o = 8; o > 0; o >>= 1) {
            s += __shfl_down_sync(0xffffffffu, s, o);
            c += __shfl_down_sync(0xffffffffu, c, o);
        }
        if (lane == 0) {
            atomicAdd(&g_sum, s);
            atomicAdd(&g_count, c);
        }
    }

    // ---------------- finalize (last block) ----------------
    __threadfence();
    if (threadIdx.x == 0) {
        unsigned int prev = atomicAdd(&g_bar2, 1u);
        if (prev == (unsigned int)nblocks - 1u) {
            float fs = *(volatile float*)&g_sum;
            unsigned int fc = *(volatile unsigned int*)&g_count;
            if (fc < 1u) fc = 1u;
            out[0] = fs / (float)fc;
            // reset state for next replay (all bar1 spinners have exited:
            // every block incremented bar2 only after passing bar1)
            g_sum = 0.0f;
            g_count = 0u;
            g_bar1 = 0u;
            g_bar2 = 0u;
        }
    }
}

extern "C" void kernel_launch(void* const* d_in, const int* in_sizes, int n_in,
                              void* d_out, int out_size) {
    const float* points = (const float*)d_in[0];   // (B, N, 3)
    const float* dens   = (const float*)d_in[1];   // (B, N, 1)
    const float* depth  = (const float*)d_in[2];   // (B, 1, H, W)
    float* out = (float*)d_out;

    int B = in_sizes[2] / PIX;                     // 8
    int N = in_sizes[0] / (3 * B);                 // 500000

    int blocksPerBatch = NBLOCKS / B;              // 55
    if (blocksPerBatch < 1) blocksPerBatch = 1;
    int nblocks = blocksPerBatch * B;              // 440 for B=8

    fused_kernel<<<nblocks, TPB>>>(points, dens, depth, out,
                                   N, B, blocksPerBatch, nblocks);
}